// round 8
// baseline (speedup 1.0000x reference)
#include <cuda_runtime.h>
#include <cuda_bf16.h>
#include <cstdint>

#define NB 256
#define NH 256
#define NT 512
#define NL 128
#define NCTA 96
#define NTHR 512

// smem byte offsets: A tile 128 rows x 1024B, B tile 64 rows x 1024B
#define OFF_A    0
#define OFF_B    131072
#define ZS_STRIDE 68
#define OFF_ZS   OFF_B                                    // overlays B after MMA
#define OFF_YS   (OFF_B + 128 * ZS_STRIDE * 4)            // after zs
#define SMEM_BYTES (131072 + 65536)                       // 192 KB

// ---- global state (3-deep ring buffers) ----
__device__ uint32_t g_H0[3][NB * NH];          // packed (lo<<16)|hi bf16 of h0, [n][k]
__device__ uint32_t g_H1[3][NB * NH];
__device__ float    g_P[3][32][128 * 64];      // layer1 x-partials [buf][pid][r][n]
__device__ float    g_Y[3][8][NB];             // y partials [buf][mu][b]

// ---- sync flags, 32B padded each (zeroed by host memset every launch) ----
// layout (index*8): R0(nu)=nu, R2(nu)=4+nu, A0R1(nu)=8+nu, RP(pid)=12+pid,
//                   AP(pid)=44+pid, START=76
#define NFLAGS 77
__device__ int g_flags[NFLAGS * 8];
#define FLG(i) (&g_flags[(i) * 8])
#define F_R0(nu)   FLG(nu)
#define F_R2(nu)   FLG(4 + (nu))
#define F_A0R1(nu) FLG(8 + (nu))
#define F_RP(pid)  FLG(12 + (pid))
#define F_AP(pid)  FLG(44 + (pid))
#define F_START    FLG(76)

// ---------------- helpers ----------------
__device__ __forceinline__ float sigm(float x) {
    return __fdividef(1.0f, 1.0f + __expf(-x));
}
__device__ __forceinline__ float tanh_f(float x) {
    float e = __expf(2.0f * x);
    return 1.0f - __fdividef(2.0f, e + 1.0f);
}
__device__ __forceinline__ uint32_t s2u(const void* p) {
    uint32_t a;
    asm("{.reg .u64 t; cvta.to.shared.u64 t, %1; cvt.u32.u64 %0, t;}" : "=r"(a) : "l"(p));
    return a;
}
__device__ __forceinline__ uint32_t cvt2(float x, float y) {
    uint32_t r;
    asm("cvt.rn.bf16x2.f32 %0, %1, %2;" : "=r"(r) : "f"(y), "f"(x));
    return r;
}
__device__ __forceinline__ float bf_lo(uint32_t u) {
    __nv_bfloat16_raw r; r.x = (unsigned short)(u & 0xffff);
    return __bfloat162float(*(__nv_bfloat16*)&r);
}
__device__ __forceinline__ float bf_hi(uint32_t u) {
    __nv_bfloat16_raw r; r.x = (unsigned short)(u >> 16);
    return __bfloat162float(*(__nv_bfloat16*)&r);
}
__device__ __forceinline__ void split2(float x, float y, uint32_t& hi, uint32_t& lo) {
    hi = cvt2(x, y);
    lo = cvt2(x - bf_lo(hi), y - bf_hi(hi));
}
__device__ __forceinline__ uint32_t packh(float h) {
    uint32_t p = cvt2(h, 0.f);
    uint32_t hb = p & 0xffff;
    float lo = h - bf_lo(p);
    uint32_t l2 = cvt2(lo, 0.f) & 0xffff;
    return (l2 << 16) | hb;
}
__device__ __forceinline__ void ldsm4(uint32_t* r, uint32_t addr) {
    asm volatile("ldmatrix.sync.aligned.m8n8.x4.shared.b16 {%0,%1,%2,%3}, [%4];"
                 : "=r"(r[0]), "=r"(r[1]), "=r"(r[2]), "=r"(r[3]) : "r"(addr));
}
__device__ __forceinline__ void mma16816(float* c, const uint32_t* a, const uint32_t* b) {
    asm volatile(
        "mma.sync.aligned.m16n8k16.row.col.f32.bf16.bf16.f32 "
        "{%0,%1,%2,%3}, {%4,%5,%6,%7}, {%8,%9}, {%0,%1,%2,%3};"
        : "+f"(c[0]), "+f"(c[1]), "+f"(c[2]), "+f"(c[3])
        : "r"(a[0]), "r"(a[1]), "r"(a[2]), "r"(a[3]), "r"(b[0]), "r"(b[1]));
}
__device__ __forceinline__ void wait_ge(volatile int* p, int target) {
    if (target <= 0) return;
    while (*p < target) { }
}

// ---- B-tile stage: packed h [n][k] -> smem [hhi|hlo], swizzled ----
__device__ __forceinline__ void stage_B(char* smem, const uint32_t* src,
                                        int nbase, int tid) {
#pragma unroll
    for (int i = 0; i < 4; i++) {
        int idx = tid + i * NTHR;          // 0..2047
        int n = idx >> 5, kg = idx & 31;
        const uint4* gp = (const uint4*)(src + (nbase + n) * NH + kg * 8);
        uint4 a = __ldcg(gp);
        uint4 b = __ldcg(gp + 1);
        uint32_t h0 = __byte_perm(a.x, a.y, 0x5410), h1 = __byte_perm(a.z, a.w, 0x5410);
        uint32_t h2 = __byte_perm(b.x, b.y, 0x5410), h3 = __byte_perm(b.z, b.w, 0x5410);
        uint32_t l0 = __byte_perm(a.x, a.y, 0x7632), l1 = __byte_perm(a.z, a.w, 0x7632);
        uint32_t l2 = __byte_perm(b.x, b.y, 0x7632), l3 = __byte_perm(b.z, b.w, 0x7632);
        int swn = n & 7;
        *(uint4*)(smem + OFF_B + n * 1024 + ((kg ^ swn) << 4))        = make_uint4(h0, h1, h2, h3);
        *(uint4*)(smem + OFF_B + n * 1024 + (((32 + kg) ^ swn) << 4)) = make_uint4(l0, l1, l2, l3);
    }
}

// ---- software-pipelined warp MMA: D[16x32], 3 passes (hh, hl, lh) ----
__device__ __forceinline__ void mma_tile(float acc[4][4], uint32_t aBase,
                                         const uint32_t* bBase, int aSel,
                                         int bSel, int swk) {
    uint32_t ah[2][4], al[2][4], bh[2][2][4], bl[2][2][4];
#define LOAD6(sl, ca_) do { \
    int c0h_ = 2 * (ca_), c0l_ = 32 + 2 * (ca_); \
    ldsm4(ah[sl], aBase + (((c0h_ + aSel) ^ swk) << 4)); \
    ldsm4(al[sl], aBase + (((c0l_ + aSel) ^ swk) << 4)); \
    ldsm4(bh[sl][0], bBase[0] + (((c0h_ + bSel) ^ swk) << 4)); \
    ldsm4(bl[sl][0], bBase[0] + (((c0l_ + bSel) ^ swk) << 4)); \
    ldsm4(bh[sl][1], bBase[1] + (((c0h_ + bSel) ^ swk) << 4)); \
    ldsm4(bl[sl][1], bBase[1] + (((c0l_ + bSel) ^ swk) << 4)); \
} while (0)
    LOAD6(0, 0);
#pragma unroll 2
    for (int ca = 0; ca < 16; ca++) {
        const int cur = ca & 1, nxt = cur ^ 1;
        if (ca < 15) LOAD6(nxt, ca + 1);
#pragma unroll
        for (int nt = 0; nt < 4; nt++) {
            const uint32_t* bhf = &bh[cur][nt >> 1][(nt & 1) * 2];
            const uint32_t* blf = &bl[cur][nt >> 1][(nt & 1) * 2];
            mma16816(acc[nt], ah[cur], bhf);   // Whi * Hhi
            mma16816(acc[nt], ah[cur], blf);   // Whi * Hlo
            mma16816(acc[nt], al[cur], bhf);   // Wlo * Hhi
        }
    }
#undef LOAD6
}

__global__ void __launch_bounds__(NTHR, 1)
lstm_mma_kernel(const float* __restrict__ latent,
                const float* __restrict__ W_lh,  const float* __restrict__ b_lh,
                const float* __restrict__ W_hh0, const float* __restrict__ b_ih0,
                const float* __restrict__ b_hh0,
                const float* __restrict__ W_ih1, const float* __restrict__ W_hh1,
                const float* __restrict__ b_ih1, const float* __restrict__ b_hh1,
                const float* __restrict__ W_ho,  const float* __restrict__ b_ho,
                float* __restrict__ out)
{
    extern __shared__ char smem[];
    const uint32_t sbase = s2u(smem);
    const int tid  = threadIdx.x;
    const int warp = tid >> 5;
    const int lane = tid & 31;

    const int bi   = blockIdx.x;
    const int role = bi >> 5;          // 0=hh0, 1=ih1, 2=hh1
    const int pid  = bi & 31;
    const int mu   = pid >> 2;         // unit tile (32 units)
    const int nu   = pid & 3;          // batch tile (64 batches)
    const int nbase = nu * 64;

    // ---- one-time: stage A = [Whi | Wlo] (128 rows x 512 k bf16, swizzled) ----
    {
        const float* Wsrc = (role == 0) ? W_hh0 : (role == 1) ? W_ih1 : W_hh1;
        for (int i = 0; i < 8; i++) {
            int idx = tid + i * NTHR;          // 0..4095
            int r = idx >> 5, kg = idx & 31;   // A-row, 8-col group
            int grow = (r & 3) * 256 + mu * 32 + (r >> 2);
            const float4* gp = (const float4*)(Wsrc + grow * 256 + kg * 8);
            float4 f0 = gp[0], f1 = gp[1];
            uint32_t h0, h1, h2, h3, l0, l1, l2, l3;
            split2(f0.x, f0.y, h0, l0);
            split2(f0.z, f0.w, h1, l1);
            split2(f1.x, f1.y, h2, l2);
            split2(f1.z, f1.w, h3, l3);
            int swr = r & 7;
            *(uint4*)(smem + OFF_A + r * 1024 + ((kg ^ swr) << 4))        = make_uint4(h0, h1, h2, h3);
            *(uint4*)(smem + OFF_A + r * 1024 + (((32 + kg) ^ swr) << 4)) = make_uint4(l0, l1, l2, l3);
        }
    }

    // ---- epilogue-thread constants: thread -> (unit jl, 4-col group cg4) ----
    const int jl  = tid >> 4;          // 0..31
    const int cg4 = tid & 15;          // 0..15
    const int j   = mu * 32 + jl;
    float bias[4] = {0.f, 0.f, 0.f, 0.f};
    if (role == 0) {
#pragma unroll
        for (int g = 0; g < 4; g++) bias[g] = b_ih0[g * NH + j] + b_hh0[g * NH + j];
    } else if (role == 2) {
#pragma unroll
        for (int g = 0; g < 4; g++) bias[g] = b_ih1[g * NH + j] + b_hh1[g * NH + j];
    }
    const float who = W_ho[j];
    const float bho = b_ho[0];

    // ---- init: h_init = latent @ W_lh.T + b_lh (roles 0,2 write h0(0)/h1(0)) ----
    if (role != 1) {
        uint32_t* dst = (role == 0) ? g_H0[0] : g_H1[0];
        for (int i = 0; i < 4; i++) {
            int idx = tid + i * NTHR;
            int jj = mu * 32 + (idx & 31);
            int nn = nbase + (idx >> 5);
            float acc = b_lh[jj];
            for (int k = 0; k < NL; k += 4) {
                float4 lv = *(const float4*)(latent + nn * NL + k);
                float4 wv = *(const float4*)(W_lh + jj * NL + k);
                acc += lv.x * wv.x + lv.y * wv.y + lv.z * wv.z + lv.w * wv.w;
            }
            __stcg(&dst[nn * NH + jj], packh(acc));
        }
    }

    float cst[4] = {0.f, 0.f, 0.f, 0.f};

    // ---- one-time startup barrier (all 96 CTAs) ----
    __threadfence();
    __syncthreads();
    if (tid == 0) {
        atomicAdd(F_START, 1);
        while (*(volatile int*)F_START < NCTA) { }
        __threadfence();
    }
    __syncthreads();

    // ---- ldmatrix addressing: warp -> (row tile rt, col half ch) ----
    const int rt = warp & 7;
    const int ch = warp >> 3;
    const int swk  = lane & 7;
    const uint32_t aBase = sbase + OFF_A + (uint32_t)(rt * 16 + (lane & 15)) * 1024;
    const int aSel = lane >> 4;
    uint32_t bBase[2];
#pragma unroll
    for (int p2 = 0; p2 < 2; p2++)
        bBase[p2] = sbase + OFF_B +
            (uint32_t)(ch * 32 + p2 * 16 + ((lane >> 4) << 3) + (lane & 7)) * 1024;
    const int bSel = (lane >> 3) & 1;

    float* zs = (float*)(smem + OFF_ZS);
    float* ys = (float*)(smem + OFF_YS);
    const int row0 = rt * 16 + (lane >> 2);
    const int colb = 2 * (lane & 3);

    // =====================================================================
    if (role == 0) {
        // -------- layer-0 recurrent GEMM: h0(t) = cell(W_hh0 h0(t-1)) ----
        for (int t = 1; t <= NT; t++) {
            if (tid == 0) { wait_ge(F_R0(nu), 8 * (t - 1)); __threadfence(); }
            __syncthreads();
            stage_B(smem, g_H0[(t - 1) % 3], nbase, tid);
            if (tid == 0) wait_ge(F_A0R1(nu), 8 * (t - 3));  // h0(t-3) consumers done
            __syncthreads();

            float acc[4][4];
#pragma unroll
            for (int a1 = 0; a1 < 4; a1++)
#pragma unroll
                for (int q = 0; q < 4; q++) acc[a1][q] = 0.f;
            mma_tile(acc, aBase, bBase, aSel, bSel, swk);
            __syncthreads();   // B reads done before zs overlay

#pragma unroll
            for (int nt = 0; nt < 4; nt++) {
                int c = ch * 32 + nt * 8 + colb;
                *(float2*)(zs + row0 * ZS_STRIDE + c)       = make_float2(acc[nt][0], acc[nt][1]);
                *(float2*)(zs + (row0 + 8) * ZS_STRIDE + c) = make_float2(acc[nt][2], acc[nt][3]);
            }
            __syncthreads();

            uint32_t* Hd = g_H0[t % 3];
            const int rb = jl * 4;
            float4 zi4 = *(const float4*)(zs + (rb + 0) * ZS_STRIDE + cg4 * 4);
            float4 zf4 = *(const float4*)(zs + (rb + 1) * ZS_STRIDE + cg4 * 4);
            float4 zg4 = *(const float4*)(zs + (rb + 2) * ZS_STRIDE + cg4 * 4);
            float4 zo4 = *(const float4*)(zs + (rb + 3) * ZS_STRIDE + cg4 * 4);
            float ziv[4] = {zi4.x, zi4.y, zi4.z, zi4.w};
            float zfv[4] = {zf4.x, zf4.y, zf4.z, zf4.w};
            float zgv[4] = {zg4.x, zg4.y, zg4.z, zg4.w};
            float zov[4] = {zo4.x, zo4.y, zo4.z, zo4.w};
#pragma unroll
            for (int c = 0; c < 4; c++) {
                float zi = ziv[c] + bias[0];
                float zf = zfv[c] + bias[1];
                float zg = zgv[c] + bias[2];
                float zo = zov[c] + bias[3];
                cst[c] = sigm(zf) * cst[c] + sigm(zi) * tanh_f(zg);
                float h = sigm(zo) * tanh_f(cst[c]);
                __stcg(&Hd[(nbase + cg4 * 4 + c) * NH + j], packh(h));
            }
            __threadfence();
            __syncthreads();
            if (tid == 0) atomicAdd(F_R0(nu), 1);
        }
    } else if (role == 1) {
        // -------- layer-1 input GEMM: P(s) = W_ih1 h0(s) ----
        for (int s = 1; s <= NT; s++) {
            if (tid == 0) { wait_ge(F_R0(nu), 8 * s); __threadfence(); }
            __syncthreads();
            stage_B(smem, g_H0[s % 3], nbase, tid);
            if (tid == 0) wait_ge(F_AP(pid), s - 3);   // P(s-3) consumed
            __syncthreads();
            if (tid == 0) atomicAdd(F_A0R1(nu), 1);    // done reading h0(s)

            float acc[4][4];
#pragma unroll
            for (int a1 = 0; a1 < 4; a1++)
#pragma unroll
                for (int q = 0; q < 4; q++) acc[a1][q] = 0.f;
            mma_tile(acc, aBase, bBase, aSel, bSel, swk);

            float* Pd = g_P[s % 3][pid];
#pragma unroll
            for (int nt = 0; nt < 4; nt++) {
                int c = ch * 32 + nt * 8 + colb;
                __stcg((float2*)(Pd + row0 * 64 + c), make_float2(acc[nt][0], acc[nt][1]));
                __stcg((float2*)(Pd + (row0 + 8) * 64 + c), make_float2(acc[nt][2], acc[nt][3]));
            }
            __threadfence();
            __syncthreads();
            if (tid == 0) *(volatile int*)F_RP(pid) = s;
        }
    } else {
        // -------- layer-1 recurrent: h1(r) = cell(P(r) + W_hh1 h1(r-1)) ----
        for (int r = 1; r <= NT; r++) {
            if (tid == 0) {
                wait_ge(F_R2(nu), 8 * (r - 1));
                wait_ge(F_RP(pid), r);
                __threadfence();
            }
            __syncthreads();
            stage_B(smem, g_H1[(r - 1) % 3], nbase, tid);
            __syncthreads();

            // output column r-2 (sum of Y(r-1) partials), off critical path
            if (mu == 0 && r >= 2 && tid >= 64 && tid < 128) {
                int b = tid - 64;
                float sY = bho;
#pragma unroll
                for (int m = 0; m < 8; m++)
                    sY += __ldcg(&g_Y[(r - 1) % 3][m][nbase + b]);
                out[(nbase + b) * NT + (r - 2)] = sY;
            }

            float acc[4][4];
#pragma unroll
            for (int a1 = 0; a1 < 4; a1++)
#pragma unroll
                for (int q = 0; q < 4; q++) acc[a1][q] = 0.f;
            mma_tile(acc, aBase, bBase, aSel, bSel, swk);
            __syncthreads();   // B reads done before zs overlay

            const float* Ps = g_P[r % 3][pid];
#pragma unroll
            for (int nt = 0; nt < 4; nt++) {
                int c = ch * 32 + nt * 8 + colb;
                float2 p0 = __ldcg((const float2*)(Ps + row0 * 64 + c));
                float2 p1 = __ldcg((const float2*)(Ps + (row0 + 8) * 64 + c));
                acc[nt][0] += p0.x; acc[nt][1] += p0.y;
                acc[nt][2] += p1.x; acc[nt][3] += p1.y;
                *(float2*)(zs + row0 * ZS_STRIDE + c)       = make_float2(acc[nt][0], acc[nt][1]);
                *(float2*)(zs + (row0 + 8) * ZS_STRIDE + c) = make_float2(acc[nt][2], acc[nt][3]);
            }
            __syncthreads();
            if (tid == 0) *(volatile int*)F_AP(pid) = r;   // P(r) consumed

            uint32_t* Hd = g_H1[r % 3];
            const int rb = jl * 4;
            float4 zi4 = *(const float4*)(zs + (rb + 0) * ZS_STRIDE + cg4 * 4);
            float4 zf4 = *(const float4*)(zs + (rb + 1) * ZS_STRIDE + cg4 * 4);
            float4 zg4 = *(const float4*)(zs + (rb + 2) * ZS_STRIDE + cg4 * 4);
            float4 zo4 = *(const float4*)(zs + (rb + 3) * ZS_STRIDE + cg4 * 4);
            float ziv[4] = {zi4.x, zi4.y, zi4.z, zi4.w};
            float zfv[4] = {zf4.x, zf4.y, zf4.z, zf4.w};
            float zgv[4] = {zg4.x, zg4.y, zg4.z, zg4.w};
            float zov[4] = {zo4.x, zo4.y, zo4.z, zo4.w};
#pragma unroll
            for (int c = 0; c < 4; c++) {
                float zi = ziv[c] + bias[0];
                float zf = zfv[c] + bias[1];
                float zg = zgv[c] + bias[2];
                float zo = zov[c] + bias[3];
                cst[c] = sigm(zf) * cst[c] + sigm(zi) * tanh_f(zg);
                float h = sigm(zo) * tanh_f(cst[c]);
                int col = cg4 * 4 + c;
                __stcg(&Hd[(nbase + col) * NH + j], packh(h));
                ys[col * 33 + jl] = h * who;
            }
            __syncthreads();
            if (tid < 64) {
                float sY = 0.f;
#pragma unroll
                for (int k = 0; k < 32; k++) sY += ys[tid * 33 + k];
                __stcg(&g_Y[r % 3][mu][nbase + tid], sY);
            }
            __threadfence();
            __syncthreads();
            if (tid == 0) atomicAdd(F_R2(nu), 1);
        }
        // final output column (NT-1) from Y(NT)
        if (mu == 0) {
            if (tid == 0) { wait_ge(F_R2(nu), 8 * NT); __threadfence(); }
            __syncthreads();
            if (tid >= 64 && tid < 128) {
                int b = tid - 64;
                float sY = bho;
#pragma unroll
                for (int m = 0; m < 8; m++)
                    sY += __ldcg(&g_Y[NT % 3][m][nbase + b]);
                out[(nbase + b) * NT + (NT - 1)] = sY;
            }
        }
    }
}

extern "C" void kernel_launch(void* const* d_in, const int* in_sizes, int n_in,
                              void* d_out, int out_size)
{
    (void)in_sizes; (void)n_in; (void)out_size;
    cudaFuncSetAttribute(lstm_mma_kernel,
                         cudaFuncAttributeMaxDynamicSharedMemorySize, SMEM_BYTES);
    void* flgp = nullptr;
    cudaGetSymbolAddress(&flgp, g_flags);
    cudaMemsetAsync(flgp, 0, NFLAGS * 8 * sizeof(int));

    lstm_mma_kernel<<<NCTA, NTHR, SMEM_BYTES>>>(
        (const float*)d_in[0],   // latent
        (const float*)d_in[1],   // W_lh
        (const float*)d_in[2],   // b_lh
        // d_in[3] = W_ih0 unused (layer-0 input is all-zero)
        (const float*)d_in[4],   // W_hh0
        (const float*)d_in[5],   // b_ih0
        (const float*)d_in[6],   // b_hh0
        (const float*)d_in[7],   // W_ih1
        (const float*)d_in[8],   // W_hh1
        (const float*)d_in[9],   // b_ih1
        (const float*)d_in[10],  // b_hh1
        (const float*)d_in[11],  // W_ho
        (const float*)d_in[12],  // b_ho
        (float*)d_out);
}

// round 9
// speedup vs baseline: 1.0138x; 1.0138x over previous
#include <cuda_runtime.h>
#include <cuda_bf16.h>
#include <cstdint>

#define NB 256
#define NH 256
#define NT 512
#define NL 128
#define NCTA 96
#define NTHR 256
#define NTICK (NT + 3)   // 515

// smem byte offsets: A tile 128 rows x 1024B, B tile 64 rows x 1024B
#define OFF_A    0
#define OFF_B    131072
#define ZS_STRIDE 68
#define OFF_ZS   OFF_B                                    // overlays B after MMA
#define OFF_YS   (OFF_B + 128 * ZS_STRIDE * 4)            // after zs
#define SMEM_BYTES (131072 + 65536)                       // 192 KB

// global state
__device__ uint32_t g_H0[2][NB * NH];          // packed (lo<<16)|hi bf16 of h0, [n][k]
__device__ uint32_t g_H1[2][NB * NH];
__device__ float    g_P[2][32][128 * 64];      // layer1 x-partials [buf][pid][r][n]
__device__ float    g_Y[2][8][NB];             // y partials [buf][mu][b]

// barrier state: per-CTA slots on distinct 128B lines + one epoch word.
// zeroed by host memset each launch.
#define SYNC_INTS (NCTA * 32 + 32)
__device__ int g_sync[SYNC_INTS];
#define SLOT(c) (g_sync + (c) * 32)
#define EPOCH   (g_sync + NCTA * 32)

// ---------------- helpers ----------------
__device__ __forceinline__ float sigm(float x) {
    return __fdividef(1.0f, 1.0f + __expf(-x));
}
__device__ __forceinline__ float tanh_f(float x) {
    float e = __expf(2.0f * x);
    return 1.0f - __fdividef(2.0f, e + 1.0f);
}
__device__ __forceinline__ uint32_t s2u(const void* p) {
    uint32_t a;
    asm("{.reg .u64 t; cvta.to.shared.u64 t, %1; cvt.u32.u64 %0, t;}" : "=r"(a) : "l"(p));
    return a;
}
__device__ __forceinline__ uint32_t cvt2(float x, float y) {
    uint32_t r;
    asm("cvt.rn.bf16x2.f32 %0, %1, %2;" : "=r"(r) : "f"(y), "f"(x));
    return r;
}
__device__ __forceinline__ float bf_lo(uint32_t u) {
    __nv_bfloat16_raw r; r.x = (unsigned short)(u & 0xffff);
    return __bfloat162float(*(__nv_bfloat16*)&r);
}
__device__ __forceinline__ float bf_hi(uint32_t u) {
    __nv_bfloat16_raw r; r.x = (unsigned short)(u >> 16);
    return __bfloat162float(*(__nv_bfloat16*)&r);
}
__device__ __forceinline__ void split2(float x, float y, uint32_t& hi, uint32_t& lo) {
    hi = cvt2(x, y);
    lo = cvt2(x - bf_lo(hi), y - bf_hi(hi));
}
__device__ __forceinline__ uint32_t packh(float h) {
    uint32_t p = cvt2(h, 0.f);
    uint32_t hb = p & 0xffff;
    float lo = h - bf_lo(p);
    uint32_t l2 = cvt2(lo, 0.f) & 0xffff;
    return (l2 << 16) | hb;
}
__device__ __forceinline__ void ldsm4(uint32_t* r, uint32_t addr) {
    asm volatile("ldmatrix.sync.aligned.m8n8.x4.shared.b16 {%0,%1,%2,%3}, [%4];"
                 : "=r"(r[0]), "=r"(r[1]), "=r"(r[2]), "=r"(r[3]) : "r"(addr));
}
__device__ __forceinline__ void mma16816(float* c, const uint32_t* a, const uint32_t* b) {
    asm volatile(
        "mma.sync.aligned.m16n8k16.row.col.f32.bf16.bf16.f32 "
        "{%0,%1,%2,%3}, {%4,%5,%6,%7}, {%8,%9}, {%0,%1,%2,%3};"
        : "+f"(c[0]), "+f"(c[1]), "+f"(c[2]), "+f"(c[3])
        : "r"(a[0]), "r"(a[1]), "r"(a[2]), "r"(a[3]), "r"(b[0]), "r"(b[1]));
}

__global__ void __launch_bounds__(NTHR, 1)
lstm_mma_kernel(const float* __restrict__ latent,
                const float* __restrict__ W_lh,  const float* __restrict__ b_lh,
                const float* __restrict__ W_hh0, const float* __restrict__ b_ih0,
                const float* __restrict__ b_hh0,
                const float* __restrict__ W_ih1, const float* __restrict__ W_hh1,
                const float* __restrict__ b_ih1, const float* __restrict__ b_hh1,
                const float* __restrict__ W_ho,  const float* __restrict__ b_ho,
                float* __restrict__ out)
{
    extern __shared__ char smem[];
    const uint32_t sbase = s2u(smem);
    const int tid  = threadIdx.x;
    const int warp = tid >> 5;
    const int lane = tid & 31;

    const int bi   = blockIdx.x;
    const int role = bi >> 5;          // 0=hh0, 1=ih1, 2=hh1
    const int pid  = bi & 31;
    const int mu   = pid >> 2;         // unit tile (32 units)
    const int nu   = pid & 3;          // batch tile (64 batches)
    const int nbase = nu * 64;

    // ---- one-time: stage A = [Whi | Wlo] (128 rows x 512 k bf16, swizzled) ----
    {
        const float* Wsrc = (role == 0) ? W_hh0 : (role == 1) ? W_ih1 : W_hh1;
        for (int i = 0; i < 16; i++) {
            int idx = tid + i * NTHR;          // 0..4095
            int r = idx >> 5, kg = idx & 31;   // A-row, 8-col group
            int grow = (r & 3) * 256 + mu * 32 + (r >> 2);
            const float4* gp = (const float4*)(Wsrc + grow * 256 + kg * 8);
            float4 f0 = gp[0], f1 = gp[1];
            uint32_t h0, h1, h2, h3, l0, l1, l2, l3;
            split2(f0.x, f0.y, h0, l0);
            split2(f0.z, f0.w, h1, l1);
            split2(f1.x, f1.y, h2, l2);
            split2(f1.z, f1.w, h3, l3);
            int swr = r & 7;
            *(uint4*)(smem + OFF_A + r * 1024 + ((kg ^ swr) << 4))        = make_uint4(h0, h1, h2, h3);
            *(uint4*)(smem + OFF_A + r * 1024 + (((32 + kg) ^ swr) << 4)) = make_uint4(l0, l1, l2, l3);
        }
    }

    // ---- epilogue-thread constants: thread -> (unit jl, 8-col group cg8) ----
    const int jl  = tid >> 3;          // 0..31
    const int cg8 = tid & 7;           // 0..7
    const int j   = mu * 32 + jl;
    float bias[4] = {0.f, 0.f, 0.f, 0.f};
    if (role == 0) {
#pragma unroll
        for (int g = 0; g < 4; g++) bias[g] = b_ih0[g * NH + j] + b_hh0[g * NH + j];
    } else if (role == 2) {
#pragma unroll
        for (int g = 0; g < 4; g++) bias[g] = b_ih1[g * NH + j] + b_hh1[g * NH + j];
    }
    const float who = W_ho[j];
    const float bho = b_ho[0];

    // ---- init: h_init = latent @ W_lh.T + b_lh (roles 0,2 write h0(0)/h1(0)) ----
    if (role != 1) {
        uint32_t* dst = (role == 0) ? g_H0[0] : g_H1[0];
        for (int i = 0; i < 8; i++) {
            int idx = tid + i * NTHR;                // 0..2047
            int jj = mu * 32 + (idx & 31);
            int nn = nbase + (idx >> 5);
            float acc = b_lh[jj];
            for (int k = 0; k < NL; k += 4) {
                float4 lv = *(const float4*)(latent + nn * NL + k);
                float4 wv = *(const float4*)(W_lh + jj * NL + k);
                acc += lv.x * wv.x + lv.y * wv.y + lv.z * wv.z + lv.w * wv.w;
            }
            __stcg(&dst[nn * NH + jj], packh(acc));
        }
    }

    float cst[8];
#pragma unroll
    for (int i = 0; i < 8; i++) cst[i] = 0.f;

    // ---- ldmatrix addressing: warp owns 16 rows x 64 cols ----
    const int swk  = lane & 7;
    const uint32_t aBase = sbase + OFF_A + (uint32_t)(warp * 16 + (lane & 15)) * 1024;
    const int aSel = lane >> 4;
    uint32_t bBase[4];
#pragma unroll
    for (int p = 0; p < 4; p++)
        bBase[p] = sbase + OFF_B +
            (uint32_t)(p * 16 + ((lane >> 4) << 3) + (lane & 7)) * 1024;
    const int bSel = (lane >> 3) & 1;

    float* zs = (float*)(smem + OFF_ZS);
    float* ys = (float*)(smem + OFF_YS);

    // ============== slot-broadcast barrier, seq 1 = startup ==============
    // arrive: __syncthreads; tid0: fence + store own slot.
    // root (bi 0): 96 threads spin on 96 distinct lines, then publish epoch.
    // others: tid0 polls epoch, fence, __syncthreads.
#define BAR_ARRIVE(seq) do {                                           \
        __syncthreads();                                               \
        if (tid == 0) { __threadfence(); *(volatile int*)SLOT(bi) = (seq); } \
    } while (0)
#define BAR_WAIT(seq) do {                                             \
        if (bi == 0) {                                                 \
            if (tid < NCTA) {                                          \
                while (*(volatile int*)SLOT(tid) < (seq)) { }          \
            }                                                          \
            __syncthreads();                                           \
            if (tid == 0) { __threadfence(); *(volatile int*)EPOCH = (seq); } \
            __syncthreads();                                           \
        } else {                                                       \
            if (tid == 0) {                                            \
                while (*(volatile int*)EPOCH < (seq)) { }              \
                __threadfence();                                       \
            }                                                          \
            __syncthreads();                                           \
        }                                                              \
    } while (0)

    BAR_ARRIVE(1);
    BAR_WAIT(1);

    for (int tick = 1; tick <= NTICK; tick++) {
        const bool active = (role == 0) ? (tick <= NT)
                          : (role == 1) ? (tick >= 2 && tick <= NT + 1)
                                        : (tick >= 3 && tick <= NT + 2);

        if (active) {
            // ---- stage B = [hhi | hlo] (64 n-rows x 512 k bf16, swizzled) ----
            {
                const uint32_t* src = (role == 2) ? g_H1[(tick - 1) & 1]
                                                  : g_H0[(tick - 1) & 1];
                for (int i = 0; i < 8; i++) {
                    int idx = tid + i * NTHR;         // 0..2047
                    int n = idx >> 5, kg = idx & 31;
                    const uint4* gp = (const uint4*)(src + (nbase + n) * NH + kg * 8);
                    uint4 a = __ldcg(gp);
                    uint4 b = __ldcg(gp + 1);
                    uint32_t h0 = __byte_perm(a.x, a.y, 0x5410), h1 = __byte_perm(a.z, a.w, 0x5410);
                    uint32_t h2 = __byte_perm(b.x, b.y, 0x5410), h3 = __byte_perm(b.z, b.w, 0x5410);
                    uint32_t l0 = __byte_perm(a.x, a.y, 0x7632), l1 = __byte_perm(a.z, a.w, 0x7632);
                    uint32_t l2 = __byte_perm(b.x, b.y, 0x7632), l3 = __byte_perm(b.z, b.w, 0x7632);
                    int swn = n & 7;
                    *(uint4*)(smem + OFF_B + n * 1024 + ((kg ^ swn) << 4))        = make_uint4(h0, h1, h2, h3);
                    *(uint4*)(smem + OFF_B + n * 1024 + (((32 + kg) ^ swn) << 4)) = make_uint4(l0, l1, l2, l3);
                }
            }
            __syncthreads();

            // ---- warp MMA: D[16x64] per warp, passes (Whi*Hhi, Whi*Hlo, Wlo*Hhi) ----
            float acc[8][4];
#pragma unroll
            for (int nt = 0; nt < 8; nt++)
#pragma unroll
                for (int q = 0; q < 4; q++) acc[nt][q] = 0.f;

#pragma unroll 1
            for (int ca = 0; ca < 16; ca++) {
                const int c0h = 2 * ca;        // hi half chunk base
                const int c0l = 32 + 2 * ca;   // lo half
                uint32_t ah[4], al[4], bh[4][4], bl[4][4];
                ldsm4(ah, aBase + (((c0h + aSel) ^ swk) << 4));
                ldsm4(al, aBase + (((c0l + aSel) ^ swk) << 4));
#pragma unroll
                for (int p = 0; p < 4; p++) {
                    ldsm4(bh[p], bBase[p] + (((c0h + bSel) ^ swk) << 4));
                    ldsm4(bl[p], bBase[p] + (((c0l + bSel) ^ swk) << 4));
                }
#pragma unroll
                for (int nt = 0; nt < 8; nt++) {
                    const uint32_t* bhf = &bh[nt >> 1][(nt & 1) * 2];
                    const uint32_t* blf = &bl[nt >> 1][(nt & 1) * 2];
                    mma16816(acc[nt], ah, bhf);   // Whi * Hhi
                    mma16816(acc[nt], ah, blf);   // Whi * Hlo
                    mma16816(acc[nt], al, bhf);   // Wlo * Hhi
                }
            }
            __syncthreads();   // B reads done before zs overlays B

            const int row0 = warp * 16 + (lane >> 2);
            const int colb = 2 * (lane & 3);

            if (role == 1) {
                // dump layer1 x-partials to global
                float* Pd = g_P[(tick - 1) & 1][pid];
#pragma unroll
                for (int nt = 0; nt < 8; nt++) {
                    int c = nt * 8 + colb;
                    __stcg((float2*)(Pd + row0 * 64 + c), make_float2(acc[nt][0], acc[nt][1]));
                    __stcg((float2*)(Pd + (row0 + 8) * 64 + c), make_float2(acc[nt][2], acc[nt][3]));
                }
            } else {
                if (role == 2) {
                    const float* Ps = g_P[tick & 1][pid];
#pragma unroll
                    for (int nt = 0; nt < 8; nt++) {
                        int c = nt * 8 + colb;
                        float2 p0 = __ldcg((const float2*)(Ps + row0 * 64 + c));
                        float2 p1 = __ldcg((const float2*)(Ps + (row0 + 8) * 64 + c));
                        acc[nt][0] += p0.x; acc[nt][1] += p0.y;
                        acc[nt][2] += p1.x; acc[nt][3] += p1.y;
                    }
                }
#pragma unroll
                for (int nt = 0; nt < 8; nt++) {
                    int c = nt * 8 + colb;
                    *(float2*)(zs + row0 * ZS_STRIDE + c)       = make_float2(acc[nt][0], acc[nt][1]);
                    *(float2*)(zs + (row0 + 8) * ZS_STRIDE + c) = make_float2(acc[nt][2], acc[nt][3]);
                }
                __syncthreads();

                // ---- gate nonlinearity + state update (256 threads, 8 cols) ----
                uint32_t* Hd = (role == 0) ? g_H0[tick & 1] : g_H1[tick & 1];
                const int rb = jl * 4;
                float4 zi4a = *(const float4*)(zs + (rb + 0) * ZS_STRIDE + cg8 * 8);
                float4 zi4b = *(const float4*)(zs + (rb + 0) * ZS_STRIDE + cg8 * 8 + 4);
                float4 zf4a = *(const float4*)(zs + (rb + 1) * ZS_STRIDE + cg8 * 8);
                float4 zf4b = *(const float4*)(zs + (rb + 1) * ZS_STRIDE + cg8 * 8 + 4);
                float4 zg4a = *(const float4*)(zs + (rb + 2) * ZS_STRIDE + cg8 * 8);
                float4 zg4b = *(const float4*)(zs + (rb + 2) * ZS_STRIDE + cg8 * 8 + 4);
                float4 zo4a = *(const float4*)(zs + (rb + 3) * ZS_STRIDE + cg8 * 8);
                float4 zo4b = *(const float4*)(zs + (rb + 3) * ZS_STRIDE + cg8 * 8 + 4);
                float ziv[8] = {zi4a.x, zi4a.y, zi4a.z, zi4a.w, zi4b.x, zi4b.y, zi4b.z, zi4b.w};
                float zfv[8] = {zf4a.x, zf4a.y, zf4a.z, zf4a.w, zf4b.x, zf4b.y, zf4b.z, zf4b.w};
                float zgv[8] = {zg4a.x, zg4a.y, zg4a.z, zg4a.w, zg4b.x, zg4b.y, zg4b.z, zg4b.w};
                float zov[8] = {zo4a.x, zo4a.y, zo4a.z, zo4a.w, zo4b.x, zo4b.y, zo4b.z, zo4b.w};
                float yv[8];
#pragma unroll
                for (int c = 0; c < 8; c++) {
                    float zi = ziv[c] + bias[0];
                    float zf = zfv[c] + bias[1];
                    float zg = zgv[c] + bias[2];
                    float zo = zov[c] + bias[3];
                    cst[c] = sigm(zf) * cst[c] + sigm(zi) * tanh_f(zg);
                    float h = sigm(zo) * tanh_f(cst[c]);
                    int col = cg8 * 8 + c;
                    __stcg(&Hd[(nbase + col) * NH + j], packh(h));
                    yv[c] = h * who;
                }
                if (role == 2) {
#pragma unroll
                    for (int c = 0; c < 8; c++)
                        ys[(cg8 * 8 + c) * 33 + jl] = yv[c];
                    __syncthreads();
                    if (tid < 64) {
                        float s = 0.f;
#pragma unroll
                        for (int k = 0; k < 32; k++) s += ys[tid * 33 + k];
                        __stcg(&g_Y[tick & 1][mu][nbase + tid], s);
                    }
                }
            }
        }

        // ---- barrier: arrive, out-summer in the shadow, then wait ----
        const int seq = tick + 1;
        BAR_ARRIVE(seq);

        if (role == 2 && mu == 0 && tick >= 4 && tid >= 64 && tid < 128) {
            int b = tid - 64;
            float s = bho;
#pragma unroll
            for (int m = 0; m < 8; m++)
                s += __ldcg(&g_Y[(tick - 1) & 1][m][nbase + b]);
            out[(nbase + b) * NT + (tick - 4)] = s;
        }

        BAR_WAIT(seq);
    }
}

extern "C" void kernel_launch(void* const* d_in, const int* in_sizes, int n_in,
                              void* d_out, int out_size)
{
    (void)in_sizes; (void)n_in; (void)out_size;
    cudaFuncSetAttribute(lstm_mma_kernel,
                         cudaFuncAttributeMaxDynamicSharedMemorySize, SMEM_BYTES);
    void* syncp = nullptr;
    cudaGetSymbolAddress(&syncp, g_sync);
    cudaMemsetAsync(syncp, 0, SYNC_INTS * sizeof(int));

    lstm_mma_kernel<<<NCTA, NTHR, SMEM_BYTES>>>(
        (const float*)d_in[0],   // latent
        (const float*)d_in[1],   // W_lh
        (const float*)d_in[2],   // b_lh
        // d_in[3] = W_ih0 unused (layer-0 input is all-zero)
        (const float*)d_in[4],   // W_hh0
        (const float*)d_in[5],   // b_ih0
        (const float*)d_in[6],   // b_hh0
        (const float*)d_in[7],   // W_ih1
        (const float*)d_in[8],   // W_hh1
        (const float*)d_in[9],   // b_ih1
        (const float*)d_in[10],  // b_hh1
        (const float*)d_in[11],  // W_ho
        (const float*)d_in[12],  // b_ho
        (float*)d_out);
}

// round 10
// speedup vs baseline: 1.2362x; 1.2194x over previous
#include <cuda_runtime.h>
#include <cuda_bf16.h>
#include <cstdint>

#define NB 256
#define NH 256
#define NT 512
#define NL 128
#define NCTA 96
#define NTHR 256
#define NTICK (NT + 3)   // 515

// smem: A tile 128 rows x 1024B (128KB) | B tile 512 k-rows x 128B (64KB)
#define OFF_A    0
#define OFF_B    131072
#define ZS_STRIDE 68
#define OFF_ZS   OFF_B                                    // overlays B after MMA
#define OFF_YS   (OFF_B + 128 * ZS_STRIDE * 4)            // after zs
#define SMEM_BYTES (131072 + 65536)                       // 192 KB

// ---- global state ----
// h buffers: per (buf, nu): [hi plane | lo plane], each plane [256 k][64 n] bf16
//   hi at byte k*128 + n*2, lo at +32768
__device__ uint8_t g_H0[2][4][65536];
__device__ uint8_t g_H1[2][4][65536];
__device__ float   g_P[2][32][128 * 64];      // layer1 x-partials [buf][pid][r][n]
__device__ float   g_Y[2][8][NB];             // y partials [buf][mu][b]
__device__ unsigned g_arrive;                 // zeroed by cudaMemsetAsync each launch

// ---------------- helpers ----------------
__device__ __forceinline__ float tanh_f(float x) {
    float t;
    asm("tanh.approx.f32 %0, %1;" : "=f"(t) : "f"(x));
    return t;
}
__device__ __forceinline__ float sigm(float x) {
    float t;
    asm("tanh.approx.f32 %0, %1;" : "=f"(t) : "f"(0.5f * x));
    return 0.5f * t + 0.5f;
}
__device__ __forceinline__ uint32_t s2u(const void* p) {
    uint32_t a;
    asm("{.reg .u64 t; cvta.to.shared.u64 t, %1; cvt.u32.u64 %0, t;}" : "=r"(a) : "l"(p));
    return a;
}
__device__ __forceinline__ uint32_t cvt2(float x, float y) {   // x->lo, y->hi
    uint32_t r;
    asm("cvt.rn.bf16x2.f32 %0, %1, %2;" : "=r"(r) : "f"(y), "f"(x));
    return r;
}
__device__ __forceinline__ float bf_lo(uint32_t u) {
    __nv_bfloat16_raw r; r.x = (unsigned short)(u & 0xffff);
    return __bfloat162float(*(__nv_bfloat16*)&r);
}
__device__ __forceinline__ float bf_hi(uint32_t u) {
    __nv_bfloat16_raw r; r.x = (unsigned short)(u >> 16);
    return __bfloat162float(*(__nv_bfloat16*)&r);
}
__device__ __forceinline__ void split2(float x, float y, uint32_t& hi, uint32_t& lo) {
    hi = cvt2(x, y);
    lo = cvt2(x - bf_lo(hi), y - bf_hi(hi));
}
__device__ __forceinline__ void ldsm4(uint32_t* r, uint32_t addr) {
    asm volatile("ldmatrix.sync.aligned.m8n8.x4.shared.b16 {%0,%1,%2,%3}, [%4];"
                 : "=r"(r[0]), "=r"(r[1]), "=r"(r[2]), "=r"(r[3]) : "r"(addr));
}
__device__ __forceinline__ void ldsm4t(uint32_t* r, uint32_t addr) {
    asm volatile("ldmatrix.sync.aligned.m8n8.x4.trans.shared.b16 {%0,%1,%2,%3}, [%4];"
                 : "=r"(r[0]), "=r"(r[1]), "=r"(r[2]), "=r"(r[3]) : "r"(addr));
}
__device__ __forceinline__ void mma16816(float* c, const uint32_t* a, const uint32_t* b) {
    asm volatile(
        "mma.sync.aligned.m16n8k16.row.col.f32.bf16.bf16.f32 "
        "{%0,%1,%2,%3}, {%4,%5,%6,%7}, {%8,%9}, {%0,%1,%2,%3};"
        : "+f"(c[0]), "+f"(c[1]), "+f"(c[2]), "+f"(c[3])
        : "r"(a[0]), "r"(a[1]), "r"(a[2]), "r"(a[3]), "r"(b[0]), "r"(b[1]));
}

__global__ void __launch_bounds__(NTHR, 1)
lstm_mma_kernel(const float* __restrict__ latent,
                const float* __restrict__ W_lh,  const float* __restrict__ b_lh,
                const float* __restrict__ W_hh0, const float* __restrict__ b_ih0,
                const float* __restrict__ b_hh0,
                const float* __restrict__ W_ih1, const float* __restrict__ W_hh1,
                const float* __restrict__ b_ih1, const float* __restrict__ b_hh1,
                const float* __restrict__ W_ho,  const float* __restrict__ b_ho,
                float* __restrict__ out)
{
    extern __shared__ char smem[];
    const uint32_t sbase = s2u(smem);
    const int tid  = threadIdx.x;
    const int warp = tid >> 5;
    const int lane = tid & 31;

    const int bi   = blockIdx.x;
    const int role = bi >> 5;          // 0=hh0, 1=ih1, 2=hh1
    const int pid  = bi & 31;
    const int mu   = pid >> 2;         // unit tile (32 units)
    const int nu   = pid & 3;          // batch tile (64 batches)
    const int nbase = nu * 64;

    // ---- one-time: stage A = [Whi | Wlo] (128 rows x 512 k bf16, swizzled) ----
    {
        const float* Wsrc = (role == 0) ? W_hh0 : (role == 1) ? W_ih1 : W_hh1;
        for (int i = 0; i < 16; i++) {
            int idx = tid + i * NTHR;          // 0..4095
            int r = idx >> 5, kg = idx & 31;   // A-row, 8-col group
            int grow = (r & 3) * 256 + mu * 32 + (r >> 2);
            const float4* gp = (const float4*)(Wsrc + grow * 256 + kg * 8);
            float4 f0 = gp[0], f1 = gp[1];
            uint32_t h0, h1, h2, h3, l0, l1, l2, l3;
            split2(f0.x, f0.y, h0, l0);
            split2(f0.z, f0.w, h1, l1);
            split2(f1.x, f1.y, h2, l2);
            split2(f1.z, f1.w, h3, l3);
            int swr = r & 7;
            *(uint4*)(smem + OFF_A + r * 1024 + ((kg ^ swr) << 4))        = make_uint4(h0, h1, h2, h3);
            *(uint4*)(smem + OFF_A + r * 1024 + (((32 + kg) ^ swr) << 4)) = make_uint4(l0, l1, l2, l3);
        }
    }

    // ---- epilogue-thread constants: thread -> (unit jl, 8-col group cg8) ----
    const int jl  = tid >> 3;          // 0..31
    const int cg8 = tid & 7;           // 0..7
    const int j   = mu * 32 + jl;
    float bias[4] = {0.f, 0.f, 0.f, 0.f};
    if (role == 0) {
#pragma unroll
        for (int g = 0; g < 4; g++) bias[g] = b_ih0[g * NH + j] + b_hh0[g * NH + j];
    } else if (role == 2) {
#pragma unroll
        for (int g = 0; g < 4; g++) bias[g] = b_ih1[g * NH + j] + b_hh1[g * NH + j];
    }
    const float who = W_ho[j];
    const float bho = b_ho[0];

    // ---- init: h_init = latent @ W_lh.T + b_lh (roles 0,2 write h0(0)/h1(0)) ----
    if (role != 1) {
        uint16_t* hiP = (uint16_t*)((role == 0) ? g_H0[0][nu] : g_H1[0][nu]);
        for (int i = 0; i < 8; i++) {
            int idx = tid + i * NTHR;                // 0..2047
            int jj = mu * 32 + (idx & 31);
            int nn = idx >> 5;                       // 0..63 local batch
            float acc = b_lh[jj];
            for (int k = 0; k < NL; k += 4) {
                float4 lv = *(const float4*)(latent + (nbase + nn) * NL + k);
                float4 wv = *(const float4*)(W_lh + jj * NL + k);
                acc += lv.x * wv.x + lv.y * wv.y + lv.z * wv.z + lv.w * wv.w;
            }
            uint32_t hb = cvt2(acc, 0.f) & 0xffff;
            float lo = acc - bf_lo(hb);
            uint32_t lb = cvt2(lo, 0.f) & 0xffff;
            hiP[jj * 64 + nn]         = (uint16_t)hb;
            hiP[16384 + jj * 64 + nn] = (uint16_t)lb;
        }
    }

    float cst[8];
#pragma unroll
    for (int i = 0; i < 8; i++) cst[i] = 0.f;

    // ---- ldmatrix addressing ----
    const int swk  = lane & 7;
    const uint32_t aBase = sbase + OFF_A + (uint32_t)(warp * 16 + (lane & 15)) * 1024;
    const int aSel = lane >> 4;
    // B (trans): lane -> (k-half kh, row r7, n-tile select nsel)
    const int r7   = lane & 7;
    const int kh   = (lane >> 3) & 1;
    const int nsel = lane >> 4;
    uint32_t bOff[4];
#pragma unroll
    for (int p = 0; p < 4; p++)
        bOff[p] = sbase + OFF_B + (uint32_t)((kh * 8 + r7) * 128)
                + ((uint32_t)((p * 2 + nsel) ^ r7) << 4);

    float* zs = (float*)(smem + OFF_ZS);
    float* ys = (float*)(smem + OFF_YS);

    // ---- barrier state ----
    unsigned bar = 0;
    // startup barrier
    __syncthreads();
    if (tid == 0) {
        __threadfence();
        atomicAdd(&g_arrive, 1u);
        while (*(volatile unsigned*)&g_arrive < bar + NCTA) { }
        __threadfence();
    }
    __syncthreads();
    bar += NCTA;

    for (int tick = 1; tick <= NTICK; tick++) {
        const bool active = (role == 0) ? (tick <= NT)
                          : (role == 1) ? (tick >= 2 && tick <= NT + 1)
                                        : (tick >= 3 && tick <= NT + 2);

        if (active) {
            // ---- stage B: pure swizzled copy of [hi|lo] planes (64KB) ----
            {
                const uint4* src = (const uint4*)((role == 2)
                    ? g_H1[(tick - 1) & 1][nu] : g_H0[(tick - 1) & 1][nu]);
#pragma unroll
                for (int i = 0; i < 16; i++) {
                    int idx = tid + i * NTHR;          // 0..4095
                    int krow = idx >> 3, c = idx & 7;
                    uint4 v = __ldcg(src + idx);
                    *(uint4*)(smem + OFF_B + krow * 128 + ((c ^ (krow & 7)) << 4)) = v;
                }
            }
            __syncthreads();

            // ---- warp MMA: D[16x64] per warp, passes (Whi*Hhi, Whi*Hlo, Wlo*Hhi) ----
            float acc[8][4];
#pragma unroll
            for (int nt = 0; nt < 8; nt++)
#pragma unroll
                for (int q = 0; q < 4; q++) acc[nt][q] = 0.f;

#pragma unroll 1
            for (int ca = 0; ca < 16; ca++) {
                const int c0h = 2 * ca;        // A hi chunk base
                const int c0l = 32 + 2 * ca;   // A lo chunk base
                const uint32_t bstep = (uint32_t)ca * 2048;
                uint32_t ah[4], al[4], bh[4][4], bl[4][4];
                ldsm4(ah, aBase + (((c0h + aSel) ^ swk) << 4));
                ldsm4(al, aBase + (((c0l + aSel) ^ swk) << 4));
#pragma unroll
                for (int p = 0; p < 4; p++) {
                    ldsm4t(bh[p], bOff[p] + bstep);
                    ldsm4t(bl[p], bOff[p] + bstep + 32768);
                }
#pragma unroll
                for (int nt = 0; nt < 8; nt++) {
                    const uint32_t* bhf = &bh[nt >> 1][(nt & 1) * 2];
                    const uint32_t* blf = &bl[nt >> 1][(nt & 1) * 2];
                    mma16816(acc[nt], ah, bhf);   // Whi * Hhi
                    mma16816(acc[nt], ah, blf);   // Whi * Hlo
                    mma16816(acc[nt], al, bhf);   // Wlo * Hhi
                }
            }
            __syncthreads();   // B reads done before zs overlays B

            const int row0 = warp * 16 + (lane >> 2);
            const int colb = 2 * (lane & 3);

            if (role == 1) {
                // dump layer1 x-partials to global
                float* Pd = g_P[(tick - 1) & 1][pid];
#pragma unroll
                for (int nt = 0; nt < 8; nt++) {
                    int c = nt * 8 + colb;
                    __stcg((float2*)(Pd + row0 * 64 + c), make_float2(acc[nt][0], acc[nt][1]));
                    __stcg((float2*)(Pd + (row0 + 8) * 64 + c), make_float2(acc[nt][2], acc[nt][3]));
                }
            } else {
                if (role == 2) {
                    const float* Ps = g_P[tick & 1][pid];
#pragma unroll
                    for (int nt = 0; nt < 8; nt++) {
                        int c = nt * 8 + colb;
                        float2 p0 = __ldcg((const float2*)(Ps + row0 * 64 + c));
                        float2 p1 = __ldcg((const float2*)(Ps + (row0 + 8) * 64 + c));
                        acc[nt][0] += p0.x; acc[nt][1] += p0.y;
                        acc[nt][2] += p1.x; acc[nt][3] += p1.y;
                    }
                }
#pragma unroll
                for (int nt = 0; nt < 8; nt++) {
                    int c = nt * 8 + colb;
                    *(float2*)(zs + row0 * ZS_STRIDE + c)       = make_float2(acc[nt][0], acc[nt][1]);
                    *(float2*)(zs + (row0 + 8) * ZS_STRIDE + c) = make_float2(acc[nt][2], acc[nt][3]);
                }
                __syncthreads();

                // ---- gate nonlinearity + state update (256 threads, 8 cols) ----
                uint8_t* Hb = (role == 0) ? g_H0[tick & 1][nu] : g_H1[tick & 1][nu];
                const int rb = jl * 4;
                float4 zi4a = *(const float4*)(zs + (rb + 0) * ZS_STRIDE + cg8 * 8);
                float4 zi4b = *(const float4*)(zs + (rb + 0) * ZS_STRIDE + cg8 * 8 + 4);
                float4 zf4a = *(const float4*)(zs + (rb + 1) * ZS_STRIDE + cg8 * 8);
                float4 zf4b = *(const float4*)(zs + (rb + 1) * ZS_STRIDE + cg8 * 8 + 4);
                float4 zg4a = *(const float4*)(zs + (rb + 2) * ZS_STRIDE + cg8 * 8);
                float4 zg4b = *(const float4*)(zs + (rb + 2) * ZS_STRIDE + cg8 * 8 + 4);
                float4 zo4a = *(const float4*)(zs + (rb + 3) * ZS_STRIDE + cg8 * 8);
                float4 zo4b = *(const float4*)(zs + (rb + 3) * ZS_STRIDE + cg8 * 8 + 4);
                float ziv[8] = {zi4a.x, zi4a.y, zi4a.z, zi4a.w, zi4b.x, zi4b.y, zi4b.z, zi4b.w};
                float zfv[8] = {zf4a.x, zf4a.y, zf4a.z, zf4a.w, zf4b.x, zf4b.y, zf4b.z, zf4b.w};
                float zgv[8] = {zg4a.x, zg4a.y, zg4a.z, zg4a.w, zg4b.x, zg4b.y, zg4b.z, zg4b.w};
                float zov[8] = {zo4a.x, zo4a.y, zo4a.z, zo4a.w, zo4b.x, zo4b.y, zo4b.z, zo4b.w};
                float hv[8];
#pragma unroll
                for (int c = 0; c < 8; c++) {
                    float zi = ziv[c] + bias[0];
                    float zf = zfv[c] + bias[1];
                    float zg = zgv[c] + bias[2];
                    float zo = zov[c] + bias[3];
                    cst[c] = sigm(zf) * cst[c] + sigm(zi) * tanh_f(zg);
                    hv[c] = sigm(zo) * tanh_f(cst[c]);
                }
                uint32_t hiu[4], lou[4];
#pragma unroll
                for (int q = 0; q < 4; q++)
                    split2(hv[2 * q], hv[2 * q + 1], hiu[q], lou[q]);
                __stcg((uint4*)(Hb + j * 128 + cg8 * 16),
                       make_uint4(hiu[0], hiu[1], hiu[2], hiu[3]));
                __stcg((uint4*)(Hb + 32768 + j * 128 + cg8 * 16),
                       make_uint4(lou[0], lou[1], lou[2], lou[3]));

                if (role == 2) {
#pragma unroll
                    for (int c = 0; c < 8; c++)
                        ys[(cg8 * 8 + c) * 33 + jl] = hv[c] * who;
                    __syncthreads();
                    if (tid < 64) {
                        float s = 0.f;
#pragma unroll
                        for (int k = 0; k < 32; k++) s += ys[tid * 33 + k];
                        __stcg(&g_Y[tick & 1][mu][nbase + tid], s);
                    }
                }
            }
        }

        // ---- barrier: arrive, out-summer in the shadow, then wait ----
        __syncthreads();
        if (tid == 0) {
            __threadfence();
            atomicAdd(&g_arrive, 1u);
        }

        if (role == 2 && mu == 0 && tick >= 4 && tid >= 64 && tid < 128) {
            int b = tid - 64;
            float s = bho;
#pragma unroll
            for (int m = 0; m < 8; m++)
                s += __ldcg(&g_Y[(tick - 1) & 1][m][nbase + b]);
            out[(nbase + b) * NT + (tick - 4)] = s;
        }

        bar += NCTA;
        if (tid == 0) {
            while (*(volatile unsigned*)&g_arrive < bar) { }
            __threadfence();
        }
        __syncthreads();
    }
}

extern "C" void kernel_launch(void* const* d_in, const int* in_sizes, int n_in,
                              void* d_out, int out_size)
{
    (void)in_sizes; (void)n_in; (void)out_size;
    cudaFuncSetAttribute(lstm_mma_kernel,
                         cudaFuncAttributeMaxDynamicSharedMemorySize, SMEM_BYTES);
    void* barp = nullptr;
    cudaGetSymbolAddress(&barp, g_arrive);
    cudaMemsetAsync(barp, 0, sizeof(unsigned));

    lstm_mma_kernel<<<NCTA, NTHR, SMEM_BYTES>>>(
        (const float*)d_in[0],   // latent
        (const float*)d_in[1],   // W_lh
        (const float*)d_in[2],   // b_lh
        // d_in[3] = W_ih0 unused (layer-0 input is all-zero)
        (const float*)d_in[4],   // W_hh0
        (const float*)d_in[5],   // b_ih0
        (const float*)d_in[6],   // b_hh0
        (const float*)d_in[7],   // W_ih1
        (const float*)d_in[8],   // W_hh1
        (const float*)d_in[9],   // b_ih1
        (const float*)d_in[10],  // b_hh1
        (const float*)d_in[11],  // W_ho
        (const float*)d_in[12],  // b_ho
        (float*)d_out);
}

// round 11
// speedup vs baseline: 1.2534x; 1.0139x over previous
#include <cuda_runtime.h>
#include <cuda_bf16.h>
#include <cstdint>

#define NB 256
#define NH 256
#define NT 512
#define NL 128
#define NCTA 96
#define NTHR 256
#define NTICK (NT + 3)   // 515

// smem: A tile 128 rows x 1024B (128KB) | B tile 512 k-rows x 128B (64KB)
#define OFF_A    0
#define OFF_B    131072
#define ZS_STRIDE 68
#define OFF_ZS   OFF_B                                    // overlays B after MMA
#define OFF_YS   (OFF_B + 128 * ZS_STRIDE * 4)            // after zs
#define SMEM_BYTES (131072 + 65536)                       // 192 KB

// ---- global state ----
// h buffers: per (buf, nu): [hi plane | lo plane], each plane [256 k][64 n] bf16
__device__ uint8_t g_H0[2][4][65536];
__device__ uint8_t g_H1[2][4][65536];
__device__ float   g_P[2][32][128 * 64];      // layer1 x-partials [buf][pid][r][n]
__device__ float   g_Y[2][8][NB];             // y partials [buf][mu][b]
__device__ unsigned g_arrive;                 // zeroed by cudaMemsetAsync each launch

// ---------------- helpers ----------------
__device__ __forceinline__ float tanh_f(float x) {
    float t;
    asm("tanh.approx.f32 %0, %1;" : "=f"(t) : "f"(x));
    return t;
}
__device__ __forceinline__ float sigm(float x) {
    float t;
    asm("tanh.approx.f32 %0, %1;" : "=f"(t) : "f"(0.5f * x));
    return 0.5f * t + 0.5f;
}
__device__ __forceinline__ uint32_t s2u(const void* p) {
    uint32_t a;
    asm("{.reg .u64 t; cvta.to.shared.u64 t, %1; cvt.u32.u64 %0, t;}" : "=r"(a) : "l"(p));
    return a;
}
__device__ __forceinline__ uint32_t cvt2(float x, float y) {   // x->lo, y->hi
    uint32_t r;
    asm("cvt.rn.bf16x2.f32 %0, %1, %2;" : "=r"(r) : "f"(y), "f"(x));
    return r;
}
__device__ __forceinline__ float bf_lo(uint32_t u) {
    __nv_bfloat16_raw r; r.x = (unsigned short)(u & 0xffff);
    return __bfloat162float(*(__nv_bfloat16*)&r);
}
__device__ __forceinline__ float bf_hi(uint32_t u) {
    __nv_bfloat16_raw r; r.x = (unsigned short)(u >> 16);
    return __bfloat162float(*(__nv_bfloat16*)&r);
}
__device__ __forceinline__ void split2(float x, float y, uint32_t& hi, uint32_t& lo) {
    hi = cvt2(x, y);
    lo = cvt2(x - bf_lo(hi), y - bf_hi(hi));
}
__device__ __forceinline__ void ldsm4(uint32_t* r, uint32_t addr) {
    asm volatile("ldmatrix.sync.aligned.m8n8.x4.shared.b16 {%0,%1,%2,%3}, [%4];"
                 : "=r"(r[0]), "=r"(r[1]), "=r"(r[2]), "=r"(r[3]) : "r"(addr));
}
__device__ __forceinline__ void ldsm4t(uint32_t* r, uint32_t addr) {
    asm volatile("ldmatrix.sync.aligned.m8n8.x4.trans.shared.b16 {%0,%1,%2,%3}, [%4];"
                 : "=r"(r[0]), "=r"(r[1]), "=r"(r[2]), "=r"(r[3]) : "r"(addr));
}
__device__ __forceinline__ void mma16816(float* c, const uint32_t* a, const uint32_t* b) {
    asm volatile(
        "mma.sync.aligned.m16n8k16.row.col.f32.bf16.bf16.f32 "
        "{%0,%1,%2,%3}, {%4,%5,%6,%7}, {%8,%9}, {%0,%1,%2,%3};"
        : "+f"(c[0]), "+f"(c[1]), "+f"(c[2]), "+f"(c[3])
        : "r"(a[0]), "r"(a[1]), "r"(a[2]), "r"(a[3]), "r"(b[0]), "r"(b[1]));
}
__device__ __forceinline__ void cpasync16(uint32_t dst, const void* src) {
    asm volatile("cp.async.cg.shared.global [%0], [%1], 16;"
                 :: "r"(dst), "l"(src) : "memory");
}

__global__ void __launch_bounds__(NTHR, 1)
lstm_mma_kernel(const float* __restrict__ latent,
                const float* __restrict__ W_lh,  const float* __restrict__ b_lh,
                const float* __restrict__ W_hh0, const float* __restrict__ b_ih0,
                const float* __restrict__ b_hh0,
                const float* __restrict__ W_ih1, const float* __restrict__ W_hh1,
                const float* __restrict__ b_ih1, const float* __restrict__ b_hh1,
                const float* __restrict__ W_ho,  const float* __restrict__ b_ho,
                float* __restrict__ out)
{
    extern __shared__ char smem[];
    const uint32_t sbase = s2u(smem);
    const int tid  = threadIdx.x;
    const int warp = tid >> 5;
    const int lane = tid & 31;

    const int bi   = blockIdx.x;
    const int role = bi >> 5;          // 0=hh0, 1=ih1, 2=hh1
    const int pid  = bi & 31;
    const int mu   = pid >> 2;         // unit tile (32 units)
    const int nu   = pid & 3;          // batch tile (64 batches)
    const int nbase = nu * 64;

    // ---- one-time: stage A = [Whi | Wlo] (128 rows x 512 k bf16, swizzled) ----
    {
        const float* Wsrc = (role == 0) ? W_hh0 : (role == 1) ? W_ih1 : W_hh1;
        for (int i = 0; i < 16; i++) {
            int idx = tid + i * NTHR;          // 0..4095
            int r = idx >> 5, kg = idx & 31;   // A-row, 8-col group
            int grow = (r & 3) * 256 + mu * 32 + (r >> 2);
            const float4* gp = (const float4*)(Wsrc + grow * 256 + kg * 8);
            float4 f0 = gp[0], f1 = gp[1];
            uint32_t h0, h1, h2, h3, l0, l1, l2, l3;
            split2(f0.x, f0.y, h0, l0);
            split2(f0.z, f0.w, h1, l1);
            split2(f1.x, f1.y, h2, l2);
            split2(f1.z, f1.w, h3, l3);
            int swr = r & 7;
            *(uint4*)(smem + OFF_A + r * 1024 + ((kg ^ swr) << 4))        = make_uint4(h0, h1, h2, h3);
            *(uint4*)(smem + OFF_A + r * 1024 + (((32 + kg) ^ swr) << 4)) = make_uint4(l0, l1, l2, l3);
        }
    }

    // ---- epilogue-thread constants: thread -> (unit jl, 8-col group cg8) ----
    const int jl  = tid >> 3;          // 0..31
    const int cg8 = tid & 7;           // 0..7
    const int j   = mu * 32 + jl;
    float bias[4] = {0.f, 0.f, 0.f, 0.f};
    if (role == 0) {
#pragma unroll
        for (int g = 0; g < 4; g++) bias[g] = b_ih0[g * NH + j] + b_hh0[g * NH + j];
    } else if (role == 2) {
#pragma unroll
        for (int g = 0; g < 4; g++) bias[g] = b_ih1[g * NH + j] + b_hh1[g * NH + j];
    }
    const float who = W_ho[j];
    const float bho = b_ho[0];

    // ---- init: h_init = latent @ W_lh.T + b_lh (roles 0,2 write h0(0)/h1(0)) ----
    if (role != 1) {
        uint16_t* hiP = (uint16_t*)((role == 0) ? g_H0[0][nu] : g_H1[0][nu]);
        for (int i = 0; i < 8; i++) {
            int idx = tid + i * NTHR;                // 0..2047
            int jj = mu * 32 + (idx & 31);
            int nn = idx >> 5;                       // 0..63 local batch
            float acc = b_lh[jj];
            for (int k = 0; k < NL; k += 4) {
                float4 lv = *(const float4*)(latent + (nbase + nn) * NL + k);
                float4 wv = *(const float4*)(W_lh + jj * NL + k);
                acc += lv.x * wv.x + lv.y * wv.y + lv.z * wv.z + lv.w * wv.w;
            }
            uint32_t hb = cvt2(acc, 0.f) & 0xffff;
            float lo = acc - bf_lo(hb);
            uint32_t lb = cvt2(lo, 0.f) & 0xffff;
            hiP[jj * 64 + nn]         = (uint16_t)hb;
            hiP[16384 + jj * 64 + nn] = (uint16_t)lb;
        }
    }

    float cst[8];
#pragma unroll
    for (int i = 0; i < 8; i++) cst[i] = 0.f;

    // ---- ldmatrix addressing ----
    const int swk  = lane & 7;
    const uint32_t aBase = sbase + OFF_A + (uint32_t)(warp * 16 + (lane & 15)) * 1024;
    const int aSel = lane >> 4;
    const int r7   = lane & 7;
    const int kh   = (lane >> 3) & 1;
    const int nsel = lane >> 4;
    uint32_t bOff[4];
#pragma unroll
    for (int p = 0; p < 4; p++)
        bOff[p] = sbase + OFF_B + (uint32_t)((kh * 8 + r7) * 128)
                + ((uint32_t)((p * 2 + nsel) ^ r7) << 4);

    float* zs = (float*)(smem + OFF_ZS);
    float* ys = (float*)(smem + OFF_YS);

    const int row0 = warp * 16 + (lane >> 2);
    const int colb = 2 * (lane & 3);

    // ---- barrier state ----
    unsigned bar = 0;
    __syncthreads();
    if (tid == 0) {
        __threadfence();
        atomicAdd(&g_arrive, 1u);
        while (*(volatile unsigned*)&g_arrive < bar + NCTA) { }
        __threadfence();
    }
    __syncthreads();
    bar += NCTA;

    for (int tick = 1; tick <= NTICK; tick++) {
        const bool active = (role == 0) ? (tick <= NT)
                          : (role == 1) ? (tick >= 2 && tick <= NT + 1)
                                        : (tick >= 3 && tick <= NT + 2);

        if (active) {
            // ---- stage B via cp.async: swizzled copy of [hi|lo] planes ----
            {
                const uint4* src = (const uint4*)((role == 2)
                    ? g_H1[(tick - 1) & 1][nu] : g_H0[(tick - 1) & 1][nu]);
#pragma unroll
                for (int i = 0; i < 16; i++) {
                    int idx = tid + i * NTHR;          // 0..4095
                    int krow = idx >> 3, c = idx & 7;
                    cpasync16(sbase + OFF_B + krow * 128 + ((c ^ (krow & 7)) << 4),
                              src + idx);
                }
                asm volatile("cp.async.commit_group;" ::: "memory");
            }

            // ---- role2: prefetch this tick's P partials while B lands ----
            float2 pv[16];
            if (role == 2) {
                const float* Ps = g_P[tick & 1][pid];
#pragma unroll
                for (int nt = 0; nt < 8; nt++) {
                    int c = nt * 8 + colb;
                    pv[nt]     = __ldcg((const float2*)(Ps + row0 * 64 + c));
                    pv[8 + nt] = __ldcg((const float2*)(Ps + (row0 + 8) * 64 + c));
                }
            }

            asm volatile("cp.async.wait_group 0;" ::: "memory");
            __syncthreads();

            // ---- warp MMA, register double-buffered pipeline ----
            float acc[8][4];
#pragma unroll
            for (int nt = 0; nt < 8; nt++)
#pragma unroll
                for (int q = 0; q < 4; q++) acc[nt][q] = 0.f;

            uint32_t ah[2][4], al[2][4], bh[2][4][4], bl[2][4][4];
#define LOADCHUNK(sl, ca_) do {                                              \
    const int c0h_ = 2 * (ca_), c0l_ = 32 + 2 * (ca_);                       \
    const uint32_t bstep_ = (uint32_t)(ca_) * 2048;                          \
    ldsm4(ah[sl], aBase + (((c0h_ + aSel) ^ swk) << 4));                     \
    ldsm4(al[sl], aBase + (((c0l_ + aSel) ^ swk) << 4));                     \
    _Pragma("unroll")                                                        \
    for (int p = 0; p < 4; p++) {                                            \
        ldsm4t(bh[sl][p], bOff[p] + bstep_);                                 \
        ldsm4t(bl[sl][p], bOff[p] + bstep_ + 32768);                         \
    }                                                                        \
} while (0)

            LOADCHUNK(0, 0);
#pragma unroll 2
            for (int ca = 0; ca < 16; ca++) {
                const int cur = ca & 1, nxt = cur ^ 1;
                if (ca < 15) LOADCHUNK(nxt, ca + 1);
#pragma unroll
                for (int nt = 0; nt < 8; nt++) {
                    const uint32_t* bhf = &bh[cur][nt >> 1][(nt & 1) * 2];
                    const uint32_t* blf = &bl[cur][nt >> 1][(nt & 1) * 2];
                    mma16816(acc[nt], ah[cur], bhf);   // Whi * Hhi
                    mma16816(acc[nt], ah[cur], blf);   // Whi * Hlo
                    mma16816(acc[nt], al[cur], bhf);   // Wlo * Hhi
                }
            }
#undef LOADCHUNK

            if (role == 1) {
                // dump layer1 x-partials to global (no zs use, no extra sync)
                float* Pd = g_P[(tick - 1) & 1][pid];
#pragma unroll
                for (int nt = 0; nt < 8; nt++) {
                    int c = nt * 8 + colb;
                    __stcg((float2*)(Pd + row0 * 64 + c), make_float2(acc[nt][0], acc[nt][1]));
                    __stcg((float2*)(Pd + (row0 + 8) * 64 + c), make_float2(acc[nt][2], acc[nt][3]));
                }
            } else {
                if (role == 2) {
#pragma unroll
                    for (int nt = 0; nt < 8; nt++) {
                        acc[nt][0] += pv[nt].x;     acc[nt][1] += pv[nt].y;
                        acc[nt][2] += pv[8 + nt].x; acc[nt][3] += pv[8 + nt].y;
                    }
                }
                __syncthreads();   // B reads done before zs overlays B
#pragma unroll
                for (int nt = 0; nt < 8; nt++) {
                    int c = nt * 8 + colb;
                    *(float2*)(zs + row0 * ZS_STRIDE + c)       = make_float2(acc[nt][0], acc[nt][1]);
                    *(float2*)(zs + (row0 + 8) * ZS_STRIDE + c) = make_float2(acc[nt][2], acc[nt][3]);
                }
                __syncthreads();

                // ---- gate nonlinearity + state update (256 threads, 8 cols) ----
                uint8_t* Hb = (role == 0) ? g_H0[tick & 1][nu] : g_H1[tick & 1][nu];
                const int rb = jl * 4;
                float4 zi4a = *(const float4*)(zs + (rb + 0) * ZS_STRIDE + cg8 * 8);
                float4 zi4b = *(const float4*)(zs + (rb + 0) * ZS_STRIDE + cg8 * 8 + 4);
                float4 zf4a = *(const float4*)(zs + (rb + 1) * ZS_STRIDE + cg8 * 8);
                float4 zf4b = *(const float4*)(zs + (rb + 1) * ZS_STRIDE + cg8 * 8 + 4);
                float4 zg4a = *(const float4*)(zs + (rb + 2) * ZS_STRIDE + cg8 * 8);
                float4 zg4b = *(const float4*)(zs + (rb + 2) * ZS_STRIDE + cg8 * 8 + 4);
                float4 zo4a = *(const float4*)(zs + (rb + 3) * ZS_STRIDE + cg8 * 8);
                float4 zo4b = *(const float4*)(zs + (rb + 3) * ZS_STRIDE + cg8 * 8 + 4);
                float ziv[8] = {zi4a.x, zi4a.y, zi4a.z, zi4a.w, zi4b.x, zi4b.y, zi4b.z, zi4b.w};
                float zfv[8] = {zf4a.x, zf4a.y, zf4a.z, zf4a.w, zf4b.x, zf4b.y, zf4b.z, zf4b.w};
                float zgv[8] = {zg4a.x, zg4a.y, zg4a.z, zg4a.w, zg4b.x, zg4b.y, zg4b.z, zg4b.w};
                float zov[8] = {zo4a.x, zo4a.y, zo4a.z, zo4a.w, zo4b.x, zo4b.y, zo4b.z, zo4b.w};
                float hv[8];
#pragma unroll
                for (int c = 0; c < 8; c++) {
                    float zi = ziv[c] + bias[0];
                    float zf = zfv[c] + bias[1];
                    float zg = zgv[c] + bias[2];
                    float zo = zov[c] + bias[3];
                    cst[c] = sigm(zf) * cst[c] + sigm(zi) * tanh_f(zg);
                    hv[c] = sigm(zo) * tanh_f(cst[c]);
                }
                uint32_t hiu[4], lou[4];
#pragma unroll
                for (int q = 0; q < 4; q++)
                    split2(hv[2 * q], hv[2 * q + 1], hiu[q], lou[q]);
                __stcg((uint4*)(Hb + j * 128 + cg8 * 16),
                       make_uint4(hiu[0], hiu[1], hiu[2], hiu[3]));
                __stcg((uint4*)(Hb + 32768 + j * 128 + cg8 * 16),
                       make_uint4(lou[0], lou[1], lou[2], lou[3]));

                if (role == 2) {
#pragma unroll
                    for (int c = 0; c < 8; c++)
                        ys[(cg8 * 8 + c) * 33 + jl] = hv[c] * who;
                    __syncthreads();
                    if (tid < 64) {
                        float s = 0.f;
#pragma unroll
                        for (int k = 0; k < 32; k++) s += ys[tid * 33 + k];
                        __stcg(&g_Y[tick & 1][mu][nbase + tid], s);
                    }
                }
            }
        }

        // ---- barrier: arrive, out-summer in the shadow, then wait ----
        __syncthreads();
        if (tid == 0) {
            __threadfence();
            atomicAdd(&g_arrive, 1u);
        }

        if (role == 2 && mu == 0 && tick >= 4 && tid >= 64 && tid < 128) {
            int b = tid - 64;
            float s = bho;
#pragma unroll
            for (int m = 0; m < 8; m++)
                s += __ldcg(&g_Y[(tick - 1) & 1][m][nbase + b]);
            out[(nbase + b) * NT + (tick - 4)] = s;
        }

        bar += NCTA;
        if (tid == 0) {
            while (*(volatile unsigned*)&g_arrive < bar) { }
            __threadfence();
        }
        __syncthreads();
    }
}

extern "C" void kernel_launch(void* const* d_in, const int* in_sizes, int n_in,
                              void* d_out, int out_size)
{
    (void)in_sizes; (void)n_in; (void)out_size;
    cudaFuncSetAttribute(lstm_mma_kernel,
                         cudaFuncAttributeMaxDynamicSharedMemorySize, SMEM_BYTES);
    void* barp = nullptr;
    cudaGetSymbolAddress(&barp, g_arrive);
    cudaMemsetAsync(barp, 0, sizeof(unsigned));

    lstm_mma_kernel<<<NCTA, NTHR, SMEM_BYTES>>>(
        (const float*)d_in[0],   // latent
        (const float*)d_in[1],   // W_lh
        (const float*)d_in[2],   // b_lh
        // d_in[3] = W_ih0 unused (layer-0 input is all-zero)
        (const float*)d_in[4],   // W_hh0
        (const float*)d_in[5],   // b_ih0
        (const float*)d_in[6],   // b_hh0
        (const float*)d_in[7],   // W_ih1
        (const float*)d_in[8],   // W_hh1
        (const float*)d_in[9],   // b_ih1
        (const float*)d_in[10],  // b_hh1
        (const float*)d_in[11],  // W_ho
        (const float*)d_in[12],  // b_ho
        (float*)d_out);
}